// round 15
// baseline (speedup 1.0000x reference)
#include <cuda_runtime.h>
#include <cuda_fp16.h>
#include <cuda_bf16.h>
#include <cstdint>

#define N_NODES 131072
#define N_EDGES 2097152
#define E_PAD   (N_EDGES + 16 * N_NODES)   // padded CSR slots (pad-to-16)
#define N_GRAPHS 64
#define DIN 64
#define HDIM 128
#define EPSV 1e-5f

// ---------------- scratch (device globals: allocation-free) ----------------
__device__ __align__(128) __half d_h16[((size_t)N_NODES + 1) * HDIM];  // 32 MB + sentinel row
__device__ __align__(128) __nv_bfloat16 d_t16[(size_t)N_NODES * HDIM]; // 32 MB (streamed)
__device__ __align__(128) uint2  d_edge[E_PAD];                        // {col, half2 attr} 32 MB
__device__ __align__(128) int    d_degi[N_NODES];
__device__ __align__(128) int    d_cnt[N_NODES];                       // seeded with starts
__device__ __align__(128) int    d_start[N_NODES + 1];
__device__ __align__(128) float  d_inv[N_NODES];
__device__ __align__(128) int    d_bsum[128];
// layer GEMM B-fragments: [layer][hi/lo][kstep 8][ntile 16][lane 32][reg 2]
__device__ __align__(128) uint32_t d_wfrag[3 * 2 * 8 * 16 * 32 * 2];
// input GEMM B-fragments: [hi/lo][kstep 4][ntile 16][lane 32][reg 2]
__device__ __align__(128) uint32_t d_wfragin[2 * 4 * 16 * 32 * 2];
__device__ __align__(128) float  d_gsum[N_GRAPHS * HDIM];
__device__ __align__(128) float  d_gcnt[N_GRAPHS];

// ---------------- helpers ----------------
__device__ __forceinline__ void red4(float* p, float4 v) {
    asm volatile("red.global.add.v4.f32 [%0], {%1,%2,%3,%4};"
                 :: "l"(p), "f"(v.x), "f"(v.y), "f"(v.z), "f"(v.w) : "memory");
}
__device__ __forceinline__ float4 h16_to_f4(uint2 u) {
    __half2* p = (__half2*)&u;
    float2 f0 = __half22float2(p[0]);
    float2 f1 = __half22float2(p[1]);
    return make_float4(f0.x, f0.y, f1.x, f1.y);
}
__device__ __forceinline__ void mma_bf16(float* d, uint32_t a0, uint32_t a1, uint32_t a2,
                                         uint32_t a3, uint32_t b0, uint32_t b1) {
    asm volatile(
        "mma.sync.aligned.m16n8k16.row.col.f32.bf16.bf16.f32 "
        "{%0,%1,%2,%3}, {%4,%5,%6,%7}, {%8,%9}, {%0,%1,%2,%3};"
        : "+f"(d[0]), "+f"(d[1]), "+f"(d[2]), "+f"(d[3])
        : "r"(a0), "r"(a1), "r"(a2), "r"(a3), "r"(b0), "r"(b1));
}

// ---------------- K1: degree count + fused init (weight frags, zeroing) ----------------
__global__ __launch_bounds__(256) void deg_init_kernel(const int* __restrict__ row,
                                                       const float* __restrict__ Wg,
                                                       const float* __restrict__ Win) {
    int i = blockIdx.x * blockDim.x + threadIdx.x;   // 2M threads
    atomicAdd(&d_degi[row[i]], 1);

    if (i < 3 * 2 * 8 * 16 * 32 * 2) {   // 49152: layer GEMM B-frags
        int r = i & 1;
        int lane = (i >> 1) & 31;
        int nt = (i >> 6) & 15;
        int ks = (i >> 10) & 7;
        int s = (i >> 13) & 1;
        int l = i >> 14;
        int tg = lane & 3;
        int g = lane >> 2;
        int k0 = ks * 16 + tg * 2 + r * 8;
        int n = nt * 8 + g;
        float w0 = __ldg(Wg + (size_t)l * HDIM * HDIM + k0 * HDIM + n);
        float w1 = __ldg(Wg + (size_t)l * HDIM * HDIM + (k0 + 1) * HDIM + n);
        __nv_bfloat16 v0, v1;
        if (s == 0) {
            v0 = __float2bfloat16(w0);
            v1 = __float2bfloat16(w1);
        } else {
            v0 = __float2bfloat16(w0 - __bfloat162float(__float2bfloat16(w0)));
            v1 = __float2bfloat16(w1 - __bfloat162float(__float2bfloat16(w1)));
        }
        d_wfrag[i] = (uint32_t)*(uint16_t*)&v0 | ((uint32_t)*(uint16_t*)&v1 << 16);
    }
    if (i < 2 * 4 * 16 * 32 * 2) {       // 8192: input GEMM B-frags
        int r = i & 1;
        int lane = (i >> 1) & 31;
        int nt = (i >> 6) & 15;
        int ks = (i >> 10) & 3;
        int s = (i >> 12) & 1;
        int tg = lane & 3;
        int g = lane >> 2;
        int k0 = ks * 16 + tg * 2 + r * 8;
        int n = nt * 8 + g;
        float w0 = __ldg(Win + k0 * HDIM + n);
        float w1 = __ldg(Win + (k0 + 1) * HDIM + n);
        __nv_bfloat16 v0, v1;
        if (s == 0) {
            v0 = __float2bfloat16(w0);
            v1 = __float2bfloat16(w1);
        } else {
            v0 = __float2bfloat16(w0 - __bfloat162float(__float2bfloat16(w0)));
            v1 = __float2bfloat16(w1 - __bfloat162float(__float2bfloat16(w1)));
        }
        d_wfragin[i] = (uint32_t)*(uint16_t*)&v0 | ((uint32_t)*(uint16_t*)&v1 << 16);
    }
    if (i < N_GRAPHS * HDIM) d_gsum[i] = 0.0f;
    if (i < N_GRAPHS) d_gcnt[i] = 0.0f;
    if (i < 16) ((uint4*)(d_h16 + (size_t)N_NODES * HDIM))[i] = make_uint4(0, 0, 0, 0);
}

// ---------------- K2a: per-block padded-deg sums ----------------
__global__ __launch_bounds__(256) void scanA_kernel() {
    __shared__ int sp[256];
    int tid = threadIdx.x;
    int4 dv = ((const int4*)d_degi)[blockIdx.x * 256 + tid];
    int s = ((dv.x + 15) & ~15) + ((dv.y + 15) & ~15) + ((dv.z + 15) & ~15) + ((dv.w + 15) & ~15);
    sp[tid] = s;
    __syncthreads();
    for (int off = 128; off > 0; off >>= 1) {
        if (tid < off) sp[tid] += sp[tid + off];
        __syncthreads();
    }
    if (tid == 0) d_bsum[blockIdx.x] = sp[0];
}

// ---------------- K2b: scan (block-base computed inline from d_bsum) ----------------
__global__ __launch_bounds__(256) void scanC_kernel() {
    __shared__ int sp[256];
    __shared__ int sb[128];
    int tid = threadIdx.x;
    int idx = blockIdx.x * 256 + tid;

    if (tid < 128) sb[tid] = d_bsum[tid];
    __syncthreads();
    for (int off = 1; off < 128; off <<= 1) {
        int v = (tid >= off && tid < 128) ? sb[tid - off] : 0;
        __syncthreads();
        if (tid < 128) sb[tid] += v;
        __syncthreads();
    }

    int4 dv = ((const int4*)d_degi)[idx];
    int p0 = (dv.x + 15) & ~15, p1 = (dv.y + 15) & ~15;
    int p2 = (dv.z + 15) & ~15, p3 = (dv.w + 15) & ~15;
    int s = p0 + p1 + p2 + p3;
    sp[tid] = s;
    __syncthreads();
    for (int off = 1; off < 256; off <<= 1) {
        int v = (tid >= off) ? sp[tid - off] : 0;
        __syncthreads();
        sp[tid] += v;
        __syncthreads();
    }
    int bbase = sb[blockIdx.x] - d_bsum[blockIdx.x];
    int base = bbase + sp[tid] - s;
    int4 st;
    st.x = base;
    st.y = base + p0;
    st.z = st.y + p1;
    st.w = st.z + p2;
    ((int4*)d_start)[idx] = st;
    ((int4*)d_cnt)[idx] = st;
    float4 iv;
    iv.x = 1.0f / (float)max(dv.x, 1);
    iv.y = 1.0f / (float)max(dv.y, 1);
    iv.z = 1.0f / (float)max(dv.z, 1);
    iv.w = 1.0f / (float)max(dv.w, 1);
    ((float4*)d_inv)[idx] = iv;
    if (blockIdx.x == 127 && tid == 127) d_start[N_NODES] = sb[127];
}

// ---------------- K3: counting-sort + pad-tail fill (fused; disjoint slots) ----------------
__global__ __launch_bounds__(256) void build_kernel(const int* __restrict__ row,
                                                    const int* __restrict__ col,
                                                    const float* __restrict__ eattr) {
    int e = blockIdx.x * blockDim.x + threadIdx.x;   // < E_PAD
    if (e < N_EDGES) {
        // payload loads first, overlap the slot atomic
        int c = __ldg(col + e);
        float2 a = __ldg((const float2*)eattr + e);
        int r = __ldg(row + e);
        int pos = atomicAdd(&d_cnt[r], 1);           // pre-seeded with start[r]
        __half2 ah = __floats2half2_rn(a.x, a.y);
        d_edge[pos] = make_uint2((uint32_t)c, *(uint32_t*)&ah);
    } else {
        int ep = e - N_EDGES;                        // < 16*N_NODES
        int n = ep >> 4, k = ep & 15;
        int js = __ldg(d_start + n) + __ldg(d_degi + n);
        if (js + k < __ldg(d_start + n + 1))
            d_edge[js + k] = make_uint2((uint32_t)N_NODES, 0u);
    }
}

// ---------------- K5: CSR gather, factored weights + fp16 acc, 2-stage pipeline ----------------
__global__ __launch_bounds__(256) void gather_kernel(const float* __restrict__ We,
                                                     const float* __restrict__ be) {
    int lane = threadIdx.x & 31;
    int n = blockIdx.x * 8 + (threadIdx.x >> 5);

    int js = __ldg(d_start + n);
    int je = __ldg(d_start + n + 1);
    uint32_t lo8 = lane * 8;
    const char* hbase = (const char*)d_h16;

    __half2 z2 = __floats2half2_rn(0.f, 0.f);
    __half2 s0a = z2, s0b = z2, s1a = z2, s1b = z2, s2a = z2, s2b = z2;

    if (js < je) {
        uint4 er[8];
#pragma unroll
        for (int i = 0; i < 8; i++) er[i] = __ldg((const uint4*)(d_edge + js) + i);

        int j = js;
        while (true) {
            // h-row loads for current group
            uint2 hv[16];
#pragma unroll
            for (int i = 0; i < 8; i++) {
                hv[2 * i]     = __ldg((const uint2*)(hbase + ((er[i].x << 8) + lo8)));
                hv[2 * i + 1] = __ldg((const uint2*)(hbase + ((er[i].z << 8) + lo8)));
            }
            // prefetch next edge group while hv loads are in flight
            int jn = j + 16;
            bool more = jn < je;
            uint4 ern[8];
            if (more) {
#pragma unroll
                for (int i = 0; i < 8; i++) ern[i] = __ldg((const uint4*)(d_edge + jn) + i);
            }
#pragma unroll
            for (int i = 0; i < 16; i++) {
                uint32_t au = (i & 1) ? er[i >> 1].w : er[i >> 1].y;
                __half2 ah = *(__half2*)&au;
                __half2 axx = __low2half2(ah);
                __half2 ayy = __high2half2(ah);
                __half2 v0 = ((__half2*)&hv[i])[0];
                __half2 v1 = ((__half2*)&hv[i])[1];
                s0a = __hfma2(v0, axx, s0a);
                s0b = __hfma2(v1, axx, s0b);
                s1a = __hfma2(v0, ayy, s1a);
                s1b = __hfma2(v1, ayy, s1b);
                s2a = __hadd2(s2a, v0);
                s2b = __hadd2(s2b, v1);
            }
            if (!more) break;
            j = jn;
#pragma unroll
            for (int i = 0; i < 8; i++) er[i] = ern[i];
        }
    }

    // per-node combine (fp32)
    float4 w0 = __ldg((const float4*)We + lane);
    float4 w1 = __ldg((const float4*)(We + HDIM) + lane);
    float4 bb = __ldg((const float4*)be + lane);
    float2 f0a = __half22float2(s0a), f0b = __half22float2(s0b);
    float2 f1a = __half22float2(s1a), f1b = __half22float2(s1b);
    float2 f2a = __half22float2(s2a), f2b = __half22float2(s2b);

    float4 acc;
    acc.x = fmaf(w0.x, f0a.x, fmaf(w1.x, f1a.x, bb.x * f2a.x));
    acc.y = fmaf(w0.y, f0a.y, fmaf(w1.y, f1a.y, bb.y * f2a.y));
    acc.z = fmaf(w0.z, f0b.x, fmaf(w1.z, f1b.x, bb.z * f2b.x));
    acc.w = fmaf(w0.w, f0b.y, fmaf(w1.w, f1b.y, bb.w * f2b.y));

    float inv = __ldg(d_inv + n);
    float4 hv = h16_to_f4(__ldg((const uint2*)(hbase + (((uint32_t)n << 8) + lo8))));
    float tx = fmaf(acc.x, inv, hv.x);
    float ty = fmaf(acc.y, inv, hv.y);
    float tz = fmaf(acc.z, inv, hv.z);
    float tw = fmaf(acc.w, inv, hv.w);
    __nv_bfloat162 p0 = __floats2bfloat162_rn(tx, ty);
    __nv_bfloat162 p1 = __floats2bfloat162_rn(tz, tw);
    __stcs((uint2*)(d_t16 + (size_t)n * HDIM) + lane,
           make_uint2(*(uint32_t*)&p0, *(uint32_t*)&p1));   // evict-first
}

// ---------------- K6: input GEMM via mma: h16 = fp16(bf16(x) @ (Whi+Wlo) + b) ----------------
#define SMI_A_BYTES (128 * 72 * 2)            // [128][72] bf16 = 18432
#define SMI_B_BYTES 32768                     // [2][4][16][32][2] u32
#define SMI_TOT (SMI_A_BYTES + SMI_B_BYTES)
__global__ __launch_bounds__(256, 2) void ingemm_kernel(const float* __restrict__ Ax,
                                                        const float* __restrict__ bias) {
    extern __shared__ char smem[];
    __nv_bfloat16* sA = (__nv_bfloat16*)smem;        // stride 72
    uint32_t* sB = (uint32_t*)(smem + SMI_A_BYTES);

    const int tid = threadIdx.x;
    const int lane = tid & 31;
    const int wid = tid >> 5;
    const int nb = blockIdx.x * 128;

    const float4* X = (const float4*)(Ax + (size_t)nb * DIN);
#pragma unroll
    for (int i = 0; i < 8; i++) {
        int q = tid + 256 * i;
        int m = q >> 4, c0 = (q & 15) * 4;
        float4 v = __ldcs(X + q);
        __nv_bfloat162 p0 = __floats2bfloat162_rn(v.x, v.y);
        __nv_bfloat162 p1 = __floats2bfloat162_rn(v.z, v.w);
        *(uint2*)(sA + m * 72 + c0) = make_uint2(*(uint32_t*)&p0, *(uint32_t*)&p1);
    }
    const uint4* BF = (const uint4*)d_wfragin;
#pragma unroll
    for (int i = 0; i < 8; i++) {
        int q = tid + 256 * i;
        ((uint4*)sB)[q] = __ldg(BF + q);
    }
    __syncthreads();

    const int g = lane >> 2, tg = lane & 3;
    float acc[16][4];
#pragma unroll
    for (int nt = 0; nt < 16; nt++)
#pragma unroll
        for (int c = 0; c < 4; c++) acc[nt][c] = 0.f;

    const __nv_bfloat16* ar0 = sA + (wid * 16 + g) * 72;
    const __nv_bfloat16* ar1 = ar0 + 8 * 72;

#pragma unroll
    for (int ks = 0; ks < 4; ks++) {
        int k0 = ks * 16 + tg * 2;
        uint32_t a0 = *(const uint32_t*)(ar0 + k0);
        uint32_t a1 = *(const uint32_t*)(ar1 + k0);
        uint32_t a2 = *(const uint32_t*)(ar0 + k0 + 8);
        uint32_t a3 = *(const uint32_t*)(ar1 + k0 + 8);
        const uint32_t* bh = sB + (ks * 16) * 64 + lane * 2;
        const uint32_t* bl = bh + 4 * 16 * 64;
#pragma unroll
        for (int nt = 0; nt < 16; nt++) {
            uint2 bhv = *(const uint2*)(bh + nt * 64);
            uint2 blv = *(const uint2*)(bl + nt * 64);
            mma_bf16(acc[nt], a0, a1, a2, a3, bhv.x, bhv.y);
            mma_bf16(acc[nt], a0, a1, a2, a3, blv.x, blv.y);
        }
    }

    int r0 = nb + wid * 16 + g;
    __half* om0 = d_h16 + (size_t)r0 * HDIM;
    __half* om1 = om0 + 8 * HDIM;
#pragma unroll
    for (int nt = 0; nt < 16; nt++) {
        int c = nt * 8 + tg * 2;
        float b0 = __ldg(bias + c), b1 = __ldg(bias + c + 1);
        *(__half2*)(om0 + c) = __floats2half2_rn(acc[nt][0] + b0, acc[nt][1] + b1);
        *(__half2*)(om1 + c) = __floats2half2_rn(acc[nt][2] + b0, acc[nt][3] + b1);
    }
}

// ---------------- K7: mma.sync layer GEMM: h16 = fp16(relu(BN(t16 @ (Whi+Wlo) + b))) ----------------
#define SM_A_BYTES 34816                      // [128][136] bf16
#define SM_B_BYTES 65536                      // [2][8][16][32][2] u32
#define SM_TOT (SM_A_BYTES + SM_B_BYTES + 1024)
__global__ __launch_bounds__(256, 2) void mmagemm_kernel(int layer,
                                                         const float* __restrict__ bias,
                                                         const float* __restrict__ gamma,
                                                         const float* __restrict__ beta,
                                                         const float* __restrict__ mean,
                                                         const float* __restrict__ var) {
    extern __shared__ char smem[];
    __nv_bfloat16* sA = (__nv_bfloat16*)smem;                 // stride 136
    uint32_t* sB = (uint32_t*)(smem + SM_A_BYTES);
    float* sBN = (float*)(smem + SM_A_BYTES + SM_B_BYTES);

    const int tid = threadIdx.x;
    const int lane = tid & 31;
    const int wid = tid >> 5;
    const int nb = blockIdx.x * 128;

    if (tid < 128) {
        float g = __ldg(gamma + tid);
        float v = __ldg(var + tid);
        float m = __ldg(mean + tid);
        float bt = __ldg(beta + tid);
        float b = __ldg(bias + tid);
        float sc = g * rsqrtf(v + EPSV);
        sBN[tid] = sc;
        sBN[128 + tid] = fmaf(b - m, sc, bt);
    }

    const uint4* T = (const uint4*)(d_t16 + (size_t)nb * HDIM);
#pragma unroll
    for (int i = 0; i < 8; i++) {
        int q = tid + 256 * i;
        int m = q >> 4, c0 = (q & 15) * 8;
        *(uint4*)(sA + m * 136 + c0) = __ldcs(T + q);
    }
    const uint4* BF = (const uint4*)(d_wfrag + layer * 16384);
#pragma unroll
    for (int i = 0; i < 16; i++) {
        int q = tid + 256 * i;
        ((uint4*)sB)[q] = __ldg(BF + q);
    }
    __syncthreads();

    const int g = lane >> 2, tg = lane & 3;
    float acc[16][4];
#pragma unroll
    for (int nt = 0; nt < 16; nt++)
#pragma unroll
        for (int c = 0; c < 4; c++) acc[nt][c] = 0.f;

    const __nv_bfloat16* ar0 = sA + (wid * 16 + g) * 136;
    const __nv_bfloat16* ar1 = ar0 + 8 * 136;

#pragma unroll
    for (int ks = 0; ks < 8; ks++) {
        int k0 = ks * 16 + tg * 2;
        uint32_t a0 = *(const uint32_t*)(ar0 + k0);
        uint32_t a1 = *(const uint32_t*)(ar1 + k0);
        uint32_t a2 = *(const uint32_t*)(ar0 + k0 + 8);
        uint32_t a3 = *(const uint32_t*)(ar1 + k0 + 8);
        const uint32_t* bh = sB + (ks * 16) * 64 + lane * 2;
        const uint32_t* bl = bh + 8 * 16 * 64;
#pragma unroll
        for (int nt = 0; nt < 16; nt++) {
            uint2 bhv = *(const uint2*)(bh + nt * 64);
            uint2 blv = *(const uint2*)(bl + nt * 64);
            mma_bf16(acc[nt], a0, a1, a2, a3, bhv.x, bhv.y);
            mma_bf16(acc[nt], a0, a1, a2, a3, blv.x, blv.y);
        }
    }

    int r0 = nb + wid * 16 + g;
    __half* om0 = d_h16 + (size_t)r0 * HDIM;
    __half* om1 = om0 + 8 * HDIM;
#pragma unroll
    for (int nt = 0; nt < 16; nt++) {
        int c = nt * 8 + tg * 2;
        float sc0 = sBN[c], sc1 = sBN[c + 1];
        float sh0 = sBN[128 + c], sh1 = sBN[128 + c + 1];
        float o00 = fmaxf(fmaf(acc[nt][0], sc0, sh0), 0.f);
        float o01 = fmaxf(fmaf(acc[nt][1], sc1, sh1), 0.f);
        float o10 = fmaxf(fmaf(acc[nt][2], sc0, sh0), 0.f);
        float o11 = fmaxf(fmaf(acc[nt][3], sc1, sh1), 0.f);
        *(__half2*)(om0 + c) = __floats2half2_rn(o00, o01);
        *(__half2*)(om1 + c) = __floats2half2_rn(o10, o11);
    }
}

// ---------------- K8: global mean-pool (batch sorted, reads h16) ----------------
__global__ __launch_bounds__(256) void pool_kernel(const int* __restrict__ batch) {
    int tx = threadIdx.x & 31;
    int ty = threadIdx.x >> 5;
    int base = blockIdx.x * 512;

    float4 acc = make_float4(0.f, 0.f, 0.f, 0.f);
    float cnt = 0.f;
    int curg = -1;

    for (int j = 0; j < 64; j++) {
        int n = base + ty + j * 8;
        int g = __ldg(batch + n);
        if (g != curg) {
            if (curg >= 0) {
                red4(d_gsum + curg * HDIM + 4 * tx, acc);
                if (tx == 0) atomicAdd(&d_gcnt[curg], cnt);
            }
            curg = g;
            acc = make_float4(0.f, 0.f, 0.f, 0.f);
            cnt = 0.f;
        }
        float4 h4 = h16_to_f4(((const uint2*)(d_h16 + (size_t)n * HDIM))[tx]);
        acc.x += h4.x; acc.y += h4.y; acc.z += h4.z; acc.w += h4.w;
        cnt += 1.f;
    }
    if (curg >= 0) {
        red4(d_gsum + curg * HDIM + 4 * tx, acc);
        if (tx == 0) atomicAdd(&d_gcnt[curg], cnt);
    }
}

// ---------------- K9: head ----------------
__global__ __launch_bounds__(128) void final_kernel(const float* __restrict__ gx,
                                                    const float* __restrict__ Wgp,
                                                    const float* __restrict__ bgp,
                                                    const float* __restrict__ Wgc,
                                                    const float* __restrict__ bgc,
                                                    float* __restrict__ out) {
    int g = blockIdx.x;
    int t = threadIdx.x;
    __shared__ float sg[HDIM];
    __shared__ float sgp[32];

    float c = fmaxf(__ldg(&d_gcnt[g]), 1.0f);
    sg[t] = d_gsum[g * HDIM + t] / c;
    if (t < 32) {
        float acc = __ldg(bgp + t);
        for (int d = 0; d < 6; d++)
            acc = fmaf(__ldg(gx + g * 6 + d), __ldg(Wgp + d * 32 + t), acc);
        sgp[t] = fmaxf(acc, 0.f);
    }
    __syncthreads();

    float acc = __ldg(bgc + t);
#pragma unroll 4
    for (int k = 0; k < HDIM; k++)
        acc = fmaf(sg[k], __ldg(Wgc + (size_t)k * HDIM + t), acc);
#pragma unroll 4
    for (int k = 0; k < 32; k++)
        acc = fmaf(sgp[k], __ldg(Wgc + (size_t)(HDIM + k) * HDIM + t), acc);
    out[g * HDIM + t] = acc;
}

// ---------------- launch ----------------
extern "C" void kernel_launch(void* const* d_in, const int* in_sizes, int n_in,
                              void* d_out, int out_size) {
    const float* x       = (const float*)d_in[0];
    const float* eattr   = (const float*)d_in[1];
    const float* gx      = (const float*)d_in[2];
    const float* W_in    = (const float*)d_in[3];
    const float* b_in    = (const float*)d_in[4];
    const float* W_edge  = (const float*)d_in[5];
    const float* b_edge  = (const float*)d_in[6];
    const float* W_gcn   = (const float*)d_in[7];
    const float* b_gcn   = (const float*)d_in[8];
    const float* bn_g    = (const float*)d_in[9];
    const float* bn_b    = (const float*)d_in[10];
    const float* bn_m    = (const float*)d_in[11];
    const float* bn_v    = (const float*)d_in[12];
    const float* W_gproj = (const float*)d_in[13];
    const float* b_gproj = (const float*)d_in[14];
    const float* W_gcomb = (const float*)d_in[15];
    const float* b_gcomb = (const float*)d_in[16];
    const int*   row     = (const int*)d_in[17];
    const int*   col     = (const int*)d_in[18];
    const int*   batch   = (const int*)d_in[19];
    float* out = (float*)d_out;

    cudaFuncSetAttribute(ingemm_kernel, cudaFuncAttributeMaxDynamicSharedMemorySize,
                         SMI_TOT);
    cudaFuncSetAttribute(mmagemm_kernel, cudaFuncAttributeMaxDynamicSharedMemorySize,
                         SM_TOT);

    void* degi_ptr = nullptr;
    cudaGetSymbolAddress(&degi_ptr, d_degi);
    cudaMemsetAsync(degi_ptr, 0, N_NODES * sizeof(int));

    deg_init_kernel<<<N_EDGES / 256, 256>>>(row, W_gcn, W_in);
    scanA_kernel<<<128, 256>>>();
    scanC_kernel<<<128, 256>>>();
    build_kernel<<<E_PAD / 256, 256>>>(row, col, eattr);

    ingemm_kernel<<<N_NODES / 128, 256, SMI_TOT>>>(x, b_in);

    for (int l = 0; l < 3; l++) {
        gather_kernel<<<N_NODES / 8, 256>>>(W_edge, b_edge);
        mmagemm_kernel<<<N_NODES / 128, 256, SM_TOT>>>(
            l, b_gcn + l * HDIM,
            bn_g + l * HDIM, bn_b + l * HDIM, bn_m + l * HDIM, bn_v + l * HDIM);
    }

    pool_kernel<<<N_NODES / 512, 256>>>(batch);
    final_kernel<<<N_GRAPHS, HDIM>>>(gx, W_gproj, b_gproj, W_gcomb, b_gcomb, out);
}

// round 16
// speedup vs baseline: 1.1536x; 1.1536x over previous
#include <cuda_runtime.h>
#include <cuda_fp16.h>
#include <cuda_bf16.h>
#include <cstdint>

#define N_NODES 131072
#define N_EDGES 2097152
#define E_PAD   (N_EDGES + 16 * N_NODES)   // padded CSR slots (pad-to-16)
#define N_GRAPHS 64
#define DIN 64
#define HDIM 128
#define EPSV 1e-5f

// ---------------- scratch (device globals: allocation-free) ----------------
__device__ __align__(128) __half d_h16[((size_t)N_NODES + 1) * HDIM];  // 32 MB + sentinel row
__device__ __align__(128) __nv_bfloat16 d_t16[(size_t)N_NODES * HDIM]; // 32 MB (streamed)
__device__ __align__(128) uint2  d_edge[E_PAD];                        // {col, half2 attr} 32 MB
__device__ __align__(128) int    d_degi[N_NODES];
__device__ __align__(128) int    d_cnt[N_NODES];                       // seeded with starts
__device__ __align__(128) int    d_start[N_NODES + 1];
__device__ __align__(128) float  d_inv[N_NODES];
__device__ __align__(128) int    d_bsum[128];
// layer GEMM B-fragments: [layer][hi/lo][kstep 8][ntile 16][lane 32][reg 2]
__device__ __align__(128) uint32_t d_wfrag[3 * 2 * 8 * 16 * 32 * 2];
// input GEMM B-fragments: [hi/lo][kstep 4][ntile 16][lane 32][reg 2]
__device__ __align__(128) uint32_t d_wfragin[2 * 4 * 16 * 32 * 2];
__device__ __align__(128) float  d_gsum[N_GRAPHS * HDIM];
__device__ __align__(128) float  d_gcnt[N_GRAPHS];

// ---------------- helpers ----------------
__device__ __forceinline__ void red4(float* p, float4 v) {
    asm volatile("red.global.add.v4.f32 [%0], {%1,%2,%3,%4};"
                 :: "l"(p), "f"(v.x), "f"(v.y), "f"(v.z), "f"(v.w) : "memory");
}
__device__ __forceinline__ float4 h16_to_f4(uint2 u) {
    __half2* p = (__half2*)&u;
    float2 f0 = __half22float2(p[0]);
    float2 f1 = __half22float2(p[1]);
    return make_float4(f0.x, f0.y, f1.x, f1.y);
}
__device__ __forceinline__ void mma_bf16(float* d, uint32_t a0, uint32_t a1, uint32_t a2,
                                         uint32_t a3, uint32_t b0, uint32_t b1) {
    asm volatile(
        "mma.sync.aligned.m16n8k16.row.col.f32.bf16.bf16.f32 "
        "{%0,%1,%2,%3}, {%4,%5,%6,%7}, {%8,%9}, {%0,%1,%2,%3};"
        : "+f"(d[0]), "+f"(d[1]), "+f"(d[2]), "+f"(d[3])
        : "r"(a0), "r"(a1), "r"(a2), "r"(a3), "r"(b0), "r"(b1));
}

// ---------------- K1: degree count + fused init (weight frags, zeroing) ----------------
__global__ __launch_bounds__(256) void deg_init_kernel(const int* __restrict__ row,
                                                       const float* __restrict__ Wg,
                                                       const float* __restrict__ Win) {
    int i = blockIdx.x * blockDim.x + threadIdx.x;   // 2M threads
    atomicAdd(&d_degi[row[i]], 1);

    if (i < 3 * 2 * 8 * 16 * 32 * 2) {   // 49152: layer GEMM B-frags
        int r = i & 1;
        int lane = (i >> 1) & 31;
        int nt = (i >> 6) & 15;
        int ks = (i >> 10) & 7;
        int s = (i >> 13) & 1;
        int l = i >> 14;
        int tg = lane & 3;
        int g = lane >> 2;
        int k0 = ks * 16 + tg * 2 + r * 8;
        int n = nt * 8 + g;
        float w0 = __ldg(Wg + (size_t)l * HDIM * HDIM + k0 * HDIM + n);
        float w1 = __ldg(Wg + (size_t)l * HDIM * HDIM + (k0 + 1) * HDIM + n);
        __nv_bfloat16 v0, v1;
        if (s == 0) {
            v0 = __float2bfloat16(w0);
            v1 = __float2bfloat16(w1);
        } else {
            v0 = __float2bfloat16(w0 - __bfloat162float(__float2bfloat16(w0)));
            v1 = __float2bfloat16(w1 - __bfloat162float(__float2bfloat16(w1)));
        }
        d_wfrag[i] = (uint32_t)*(uint16_t*)&v0 | ((uint32_t)*(uint16_t*)&v1 << 16);
    }
    if (i < 2 * 4 * 16 * 32 * 2) {       // 8192: input GEMM B-frags
        int r = i & 1;
        int lane = (i >> 1) & 31;
        int nt = (i >> 6) & 15;
        int ks = (i >> 10) & 3;
        int s = (i >> 12) & 1;
        int tg = lane & 3;
        int g = lane >> 2;
        int k0 = ks * 16 + tg * 2 + r * 8;
        int n = nt * 8 + g;
        float w0 = __ldg(Win + k0 * HDIM + n);
        float w1 = __ldg(Win + (k0 + 1) * HDIM + n);
        __nv_bfloat16 v0, v1;
        if (s == 0) {
            v0 = __float2bfloat16(w0);
            v1 = __float2bfloat16(w1);
        } else {
            v0 = __float2bfloat16(w0 - __bfloat162float(__float2bfloat16(w0)));
            v1 = __float2bfloat16(w1 - __bfloat162float(__float2bfloat16(w1)));
        }
        d_wfragin[i] = (uint32_t)*(uint16_t*)&v0 | ((uint32_t)*(uint16_t*)&v1 << 16);
    }
    if (i < N_GRAPHS * HDIM) d_gsum[i] = 0.0f;
    if (i < N_GRAPHS) d_gcnt[i] = 0.0f;
    if (i < 16) ((uint4*)(d_h16 + (size_t)N_NODES * HDIM))[i] = make_uint4(0, 0, 0, 0);
}

// ---------------- K2a: per-block padded-deg sums ----------------
__global__ __launch_bounds__(256) void scanA_kernel() {
    __shared__ int sp[256];
    int tid = threadIdx.x;
    int4 dv = ((const int4*)d_degi)[blockIdx.x * 256 + tid];
    int s = ((dv.x + 15) & ~15) + ((dv.y + 15) & ~15) + ((dv.z + 15) & ~15) + ((dv.w + 15) & ~15);
    sp[tid] = s;
    __syncthreads();
    for (int off = 128; off > 0; off >>= 1) {
        if (tid < off) sp[tid] += sp[tid + off];
        __syncthreads();
    }
    if (tid == 0) d_bsum[blockIdx.x] = sp[0];
}

// ---------------- K2b: scan (block-base computed inline from d_bsum) ----------------
__global__ __launch_bounds__(256) void scanC_kernel() {
    __shared__ int sp[256];
    __shared__ int sb[128];
    int tid = threadIdx.x;
    int idx = blockIdx.x * 256 + tid;

    if (tid < 128) sb[tid] = d_bsum[tid];
    __syncthreads();
    for (int off = 1; off < 128; off <<= 1) {
        int v = (tid >= off && tid < 128) ? sb[tid - off] : 0;
        __syncthreads();
        if (tid < 128) sb[tid] += v;
        __syncthreads();
    }

    int4 dv = ((const int4*)d_degi)[idx];
    int p0 = (dv.x + 15) & ~15, p1 = (dv.y + 15) & ~15;
    int p2 = (dv.z + 15) & ~15, p3 = (dv.w + 15) & ~15;
    int s = p0 + p1 + p2 + p3;
    sp[tid] = s;
    __syncthreads();
    for (int off = 1; off < 256; off <<= 1) {
        int v = (tid >= off) ? sp[tid - off] : 0;
        __syncthreads();
        sp[tid] += v;
        __syncthreads();
    }
    int bbase = sb[blockIdx.x] - d_bsum[blockIdx.x];
    int base = bbase + sp[tid] - s;
    int4 st;
    st.x = base;
    st.y = base + p0;
    st.z = st.y + p1;
    st.w = st.z + p2;
    ((int4*)d_start)[idx] = st;
    ((int4*)d_cnt)[idx] = st;
    float4 iv;
    iv.x = 1.0f / (float)max(dv.x, 1);
    iv.y = 1.0f / (float)max(dv.y, 1);
    iv.z = 1.0f / (float)max(dv.z, 1);
    iv.w = 1.0f / (float)max(dv.w, 1);
    ((float4*)d_inv)[idx] = iv;
    if (blockIdx.x == 127 && tid == 127) d_start[N_NODES] = sb[127];
}

// ---------------- K3: counting-sort + pad-tail fill (fused; disjoint slots) ----------------
__global__ __launch_bounds__(256) void build_kernel(const int* __restrict__ row,
                                                    const int* __restrict__ col,
                                                    const float* __restrict__ eattr) {
    int e = blockIdx.x * blockDim.x + threadIdx.x;   // < E_PAD
    if (e < N_EDGES) {
        int r = __ldg(row + e);
        int pos = atomicAdd(&d_cnt[r], 1);           // pre-seeded with start[r]
        float2 a = __ldg((const float2*)eattr + e);
        __half2 ah = __floats2half2_rn(a.x, a.y);
        d_edge[pos] = make_uint2((uint32_t)__ldg(col + e), *(uint32_t*)&ah);
    } else {
        int ep = e - N_EDGES;                        // < 16*N_NODES
        int n = ep >> 4, k = ep & 15;
        int js = __ldg(d_start + n) + __ldg(d_degi + n);
        if (js + k < __ldg(d_start + n + 1))
            d_edge[js + k] = make_uint2((uint32_t)N_NODES, 0u);
    }
}

// ---------------- K5: CSR gather, factored weights + fp16 accumulation ----------------
__global__ __launch_bounds__(256) void gather_kernel(const float* __restrict__ We,
                                                     const float* __restrict__ be) {
    int lane = threadIdx.x & 31;
    int n = blockIdx.x * 8 + (threadIdx.x >> 5);

    int js = __ldg(d_start + n);
    int je = __ldg(d_start + n + 1);
    uint32_t lo8 = lane * 8;
    const char* hbase = (const char*)d_h16;

    __half2 z2 = __floats2half2_rn(0.f, 0.f);
    __half2 s0a = z2, s0b = z2, s1a = z2, s1b = z2, s2a = z2, s2b = z2;

    for (int j = js; j < je; j += 16) {
        uint4 er[8];
#pragma unroll
        for (int i = 0; i < 8; i++) er[i] = __ldg((const uint4*)(d_edge + j) + i);
        uint2 hv[16];
#pragma unroll
        for (int i = 0; i < 8; i++) {
            hv[2 * i]     = __ldg((const uint2*)(hbase + ((er[i].x << 8) + lo8)));
            hv[2 * i + 1] = __ldg((const uint2*)(hbase + ((er[i].z << 8) + lo8)));
        }
#pragma unroll
        for (int i = 0; i < 16; i++) {
            uint32_t au = (i & 1) ? er[i >> 1].w : er[i >> 1].y;
            __half2 ah = *(__half2*)&au;
            __half2 axx = __low2half2(ah);
            __half2 ayy = __high2half2(ah);
            __half2 v0 = ((__half2*)&hv[i])[0];
            __half2 v1 = ((__half2*)&hv[i])[1];
            s0a = __hfma2(v0, axx, s0a);
            s0b = __hfma2(v1, axx, s0b);
            s1a = __hfma2(v0, ayy, s1a);
            s1b = __hfma2(v1, ayy, s1b);
            s2a = __hadd2(s2a, v0);
            s2b = __hadd2(s2b, v1);
        }
    }

    // per-node combine (fp32)
    float4 w0 = __ldg((const float4*)We + lane);
    float4 w1 = __ldg((const float4*)(We + HDIM) + lane);
    float4 bb = __ldg((const float4*)be + lane);
    float2 f0a = __half22float2(s0a), f0b = __half22float2(s0b);
    float2 f1a = __half22float2(s1a), f1b = __half22float2(s1b);
    float2 f2a = __half22float2(s2a), f2b = __half22float2(s2b);

    float4 acc;
    acc.x = fmaf(w0.x, f0a.x, fmaf(w1.x, f1a.x, bb.x * f2a.x));
    acc.y = fmaf(w0.y, f0a.y, fmaf(w1.y, f1a.y, bb.y * f2a.y));
    acc.z = fmaf(w0.z, f0b.x, fmaf(w1.z, f1b.x, bb.z * f2b.x));
    acc.w = fmaf(w0.w, f0b.y, fmaf(w1.w, f1b.y, bb.w * f2b.y));

    float inv = __ldg(d_inv + n);
    float4 hv = h16_to_f4(__ldg((const uint2*)(hbase + (((uint32_t)n << 8) + lo8))));
    float tx = fmaf(acc.x, inv, hv.x);
    float ty = fmaf(acc.y, inv, hv.y);
    float tz = fmaf(acc.z, inv, hv.z);
    float tw = fmaf(acc.w, inv, hv.w);
    __nv_bfloat162 p0 = __floats2bfloat162_rn(tx, ty);
    __nv_bfloat162 p1 = __floats2bfloat162_rn(tz, tw);
    __stcs((uint2*)(d_t16 + (size_t)n * HDIM) + lane,
           make_uint2(*(uint32_t*)&p0, *(uint32_t*)&p1));   // evict-first
}

// ---------------- K6: input GEMM via mma: h16 = fp16(bf16(x) @ (Whi+Wlo) + b) ----------------
#define SMI_A_BYTES (128 * 72 * 2)            // [128][72] bf16 = 18432
#define SMI_B_BYTES 32768                     // [2][4][16][32][2] u32
#define SMI_TOT (SMI_A_BYTES + SMI_B_BYTES)
__global__ __launch_bounds__(256, 2) void ingemm_kernel(const float* __restrict__ Ax,
                                                        const float* __restrict__ bias) {
    extern __shared__ char smem[];
    __nv_bfloat16* sA = (__nv_bfloat16*)smem;        // stride 72
    uint32_t* sB = (uint32_t*)(smem + SMI_A_BYTES);

    const int tid = threadIdx.x;
    const int lane = tid & 31;
    const int wid = tid >> 5;
    const int nb = blockIdx.x * 128;

    const float4* X = (const float4*)(Ax + (size_t)nb * DIN);
#pragma unroll
    for (int i = 0; i < 8; i++) {
        int q = tid + 256 * i;
        int m = q >> 4, c0 = (q & 15) * 4;
        float4 v = __ldcs(X + q);
        __nv_bfloat162 p0 = __floats2bfloat162_rn(v.x, v.y);
        __nv_bfloat162 p1 = __floats2bfloat162_rn(v.z, v.w);
        *(uint2*)(sA + m * 72 + c0) = make_uint2(*(uint32_t*)&p0, *(uint32_t*)&p1);
    }
    const uint4* BF = (const uint4*)d_wfragin;
#pragma unroll
    for (int i = 0; i < 8; i++) {
        int q = tid + 256 * i;
        ((uint4*)sB)[q] = __ldg(BF + q);
    }
    __syncthreads();

    const int g = lane >> 2, tg = lane & 3;
    float acc[16][4];
#pragma unroll
    for (int nt = 0; nt < 16; nt++)
#pragma unroll
        for (int c = 0; c < 4; c++) acc[nt][c] = 0.f;

    const __nv_bfloat16* ar0 = sA + (wid * 16 + g) * 72;
    const __nv_bfloat16* ar1 = ar0 + 8 * 72;

#pragma unroll
    for (int ks = 0; ks < 4; ks++) {
        int k0 = ks * 16 + tg * 2;
        uint32_t a0 = *(const uint32_t*)(ar0 + k0);
        uint32_t a1 = *(const uint32_t*)(ar1 + k0);
        uint32_t a2 = *(const uint32_t*)(ar0 + k0 + 8);
        uint32_t a3 = *(const uint32_t*)(ar1 + k0 + 8);
        const uint32_t* bh = sB + (ks * 16) * 64 + lane * 2;
        const uint32_t* bl = bh + 4 * 16 * 64;
#pragma unroll
        for (int nt = 0; nt < 16; nt++) {
            uint2 bhv = *(const uint2*)(bh + nt * 64);
            uint2 blv = *(const uint2*)(bl + nt * 64);
            mma_bf16(acc[nt], a0, a1, a2, a3, bhv.x, bhv.y);
            mma_bf16(acc[nt], a0, a1, a2, a3, blv.x, blv.y);
        }
    }

    int r0 = nb + wid * 16 + g;
    __half* om0 = d_h16 + (size_t)r0 * HDIM;
    __half* om1 = om0 + 8 * HDIM;
#pragma unroll
    for (int nt = 0; nt < 16; nt++) {
        int c = nt * 8 + tg * 2;
        float b0 = __ldg(bias + c), b1 = __ldg(bias + c + 1);
        *(__half2*)(om0 + c) = __floats2half2_rn(acc[nt][0] + b0, acc[nt][1] + b1);
        *(__half2*)(om1 + c) = __floats2half2_rn(acc[nt][2] + b0, acc[nt][3] + b1);
    }
}

// ---------------- K7: mma.sync layer GEMM: h16 = fp16(relu(BN(t16 @ (Whi+Wlo) + b))) ----------------
#define SM_A_BYTES 34816                      // [128][136] bf16
#define SM_B_BYTES 65536                      // [2][8][16][32][2] u32
#define SM_TOT (SM_A_BYTES + SM_B_BYTES + 1024)
__global__ __launch_bounds__(256, 2) void mmagemm_kernel(int layer,
                                                         const float* __restrict__ bias,
                                                         const float* __restrict__ gamma,
                                                         const float* __restrict__ beta,
                                                         const float* __restrict__ mean,
                                                         const float* __restrict__ var) {
    extern __shared__ char smem[];
    __nv_bfloat16* sA = (__nv_bfloat16*)smem;                 // stride 136
    uint32_t* sB = (uint32_t*)(smem + SM_A_BYTES);
    float* sBN = (float*)(smem + SM_A_BYTES + SM_B_BYTES);

    const int tid = threadIdx.x;
    const int lane = tid & 31;
    const int wid = tid >> 5;
    const int nb = blockIdx.x * 128;

    if (tid < 128) {
        float g = __ldg(gamma + tid);
        float v = __ldg(var + tid);
        float m = __ldg(mean + tid);
        float bt = __ldg(beta + tid);
        float b = __ldg(bias + tid);
        float sc = g * rsqrtf(v + EPSV);
        sBN[tid] = sc;
        sBN[128 + tid] = fmaf(b - m, sc, bt);
    }

    const uint4* T = (const uint4*)(d_t16 + (size_t)nb * HDIM);
#pragma unroll
    for (int i = 0; i < 8; i++) {
        int q = tid + 256 * i;
        int m = q >> 4, c0 = (q & 15) * 8;
        *(uint4*)(sA + m * 136 + c0) = __ldcs(T + q);
    }
    const uint4* BF = (const uint4*)(d_wfrag + layer * 16384);
#pragma unroll
    for (int i = 0; i < 16; i++) {
        int q = tid + 256 * i;
        ((uint4*)sB)[q] = __ldg(BF + q);
    }
    __syncthreads();

    const int g = lane >> 2, tg = lane & 3;
    float acc[16][4];
#pragma unroll
    for (int nt = 0; nt < 16; nt++)
#pragma unroll
        for (int c = 0; c < 4; c++) acc[nt][c] = 0.f;

    const __nv_bfloat16* ar0 = sA + (wid * 16 + g) * 136;
    const __nv_bfloat16* ar1 = ar0 + 8 * 136;

#pragma unroll
    for (int ks = 0; ks < 8; ks++) {
        int k0 = ks * 16 + tg * 2;
        uint32_t a0 = *(const uint32_t*)(ar0 + k0);
        uint32_t a1 = *(const uint32_t*)(ar1 + k0);
        uint32_t a2 = *(const uint32_t*)(ar0 + k0 + 8);
        uint32_t a3 = *(const uint32_t*)(ar1 + k0 + 8);
        const uint32_t* bh = sB + (ks * 16) * 64 + lane * 2;
        const uint32_t* bl = bh + 8 * 16 * 64;
#pragma unroll
        for (int nt = 0; nt < 16; nt++) {
            uint2 bhv = *(const uint2*)(bh + nt * 64);
            uint2 blv = *(const uint2*)(bl + nt * 64);
            mma_bf16(acc[nt], a0, a1, a2, a3, bhv.x, bhv.y);
            mma_bf16(acc[nt], a0, a1, a2, a3, blv.x, blv.y);
        }
    }

    int r0 = nb + wid * 16 + g;
    __half* om0 = d_h16 + (size_t)r0 * HDIM;
    __half* om1 = om0 + 8 * HDIM;
#pragma unroll
    for (int nt = 0; nt < 16; nt++) {
        int c = nt * 8 + tg * 2;
        float sc0 = sBN[c], sc1 = sBN[c + 1];
        float sh0 = sBN[128 + c], sh1 = sBN[128 + c + 1];
        float o00 = fmaxf(fmaf(acc[nt][0], sc0, sh0), 0.f);
        float o01 = fmaxf(fmaf(acc[nt][1], sc1, sh1), 0.f);
        float o10 = fmaxf(fmaf(acc[nt][2], sc0, sh0), 0.f);
        float o11 = fmaxf(fmaf(acc[nt][3], sc1, sh1), 0.f);
        *(__half2*)(om0 + c) = __floats2half2_rn(o00, o01);
        *(__half2*)(om1 + c) = __floats2half2_rn(o10, o11);
    }
}

// ---------------- K8: global mean-pool (batch sorted, reads h16) ----------------
__global__ __launch_bounds__(256) void pool_kernel(const int* __restrict__ batch) {
    int tx = threadIdx.x & 31;
    int ty = threadIdx.x >> 5;
    int base = blockIdx.x * 512;

    float4 acc = make_float4(0.f, 0.f, 0.f, 0.f);
    float cnt = 0.f;
    int curg = -1;

    for (int j = 0; j < 64; j++) {
        int n = base + ty + j * 8;
        int g = __ldg(batch + n);
        if (g != curg) {
            if (curg >= 0) {
                red4(d_gsum + curg * HDIM + 4 * tx, acc);
                if (tx == 0) atomicAdd(&d_gcnt[curg], cnt);
            }
            curg = g;
            acc = make_float4(0.f, 0.f, 0.f, 0.f);
            cnt = 0.f;
        }
        float4 h4 = h16_to_f4(((const uint2*)(d_h16 + (size_t)n * HDIM))[tx]);
        acc.x += h4.x; acc.y += h4.y; acc.z += h4.z; acc.w += h4.w;
        cnt += 1.f;
    }
    if (curg >= 0) {
        red4(d_gsum + curg * HDIM + 4 * tx, acc);
        if (tx == 0) atomicAdd(&d_gcnt[curg], cnt);
    }
}

// ---------------- K9: head ----------------
__global__ __launch_bounds__(128) void final_kernel(const float* __restrict__ gx,
                                                    const float* __restrict__ Wgp,
                                                    const float* __restrict__ bgp,
                                                    const float* __restrict__ Wgc,
                                                    const float* __restrict__ bgc,
                                                    float* __restrict__ out) {
    int g = blockIdx.x;
    int t = threadIdx.x;
    __shared__ float sg[HDIM];
    __shared__ float sgp[32];

    float c = fmaxf(__ldg(&d_gcnt[g]), 1.0f);
    sg[t] = d_gsum[g * HDIM + t] / c;
    if (t < 32) {
        float acc = __ldg(bgp + t);
        for (int d = 0; d < 6; d++)
            acc = fmaf(__ldg(gx + g * 6 + d), __ldg(Wgp + d * 32 + t), acc);
        sgp[t] = fmaxf(acc, 0.f);
    }
    __syncthreads();

    float acc = __ldg(bgc + t);
#pragma unroll 4
    for (int k = 0; k < HDIM; k++)
        acc = fmaf(sg[k], __ldg(Wgc + (size_t)k * HDIM + t), acc);
#pragma unroll 4
    for (int k = 0; k < 32; k++)
        acc = fmaf(sgp[k], __ldg(Wgc + (size_t)(HDIM + k) * HDIM + t), acc);
    out[g * HDIM + t] = acc;
}

// ---------------- launch ----------------
extern "C" void kernel_launch(void* const* d_in, const int* in_sizes, int n_in,
                              void* d_out, int out_size) {
    const float* x       = (const float*)d_in[0];
    const float* eattr   = (const float*)d_in[1];
    const float* gx      = (const float*)d_in[2];
    const float* W_in    = (const float*)d_in[3];
    const float* b_in    = (const float*)d_in[4];
    const float* W_edge  = (const float*)d_in[5];
    const float* b_edge  = (const float*)d_in[6];
    const float* W_gcn   = (const float*)d_in[7];
    const float* b_gcn   = (const float*)d_in[8];
    const float* bn_g    = (const float*)d_in[9];
    const float* bn_b    = (const float*)d_in[10];
    const float* bn_m    = (const float*)d_in[11];
    const float* bn_v    = (const float*)d_in[12];
    const float* W_gproj = (const float*)d_in[13];
    const float* b_gproj = (const float*)d_in[14];
    const float* W_gcomb = (const float*)d_in[15];
    const float* b_gcomb = (const float*)d_in[16];
    const int*   row     = (const int*)d_in[17];
    const int*   col     = (const int*)d_in[18];
    const int*   batch   = (const int*)d_in[19];
    float* out = (float*)d_out;

    cudaFuncSetAttribute(ingemm_kernel, cudaFuncAttributeMaxDynamicSharedMemorySize,
                         SMI_TOT);
    cudaFuncSetAttribute(mmagemm_kernel, cudaFuncAttributeMaxDynamicSharedMemorySize,
                         SM_TOT);

    void* degi_ptr = nullptr;
    cudaGetSymbolAddress(&degi_ptr, d_degi);
    cudaMemsetAsync(degi_ptr, 0, N_NODES * sizeof(int));

    deg_init_kernel<<<N_EDGES / 256, 256>>>(row, W_gcn, W_in);
    scanA_kernel<<<128, 256>>>();
    scanC_kernel<<<128, 256>>>();
    build_kernel<<<E_PAD / 256, 256>>>(row, col, eattr);

    ingemm_kernel<<<N_NODES / 128, 256, SMI_TOT>>>(x, b_in);

    for (int l = 0; l < 3; l++) {
        gather_kernel<<<N_NODES / 8, 256>>>(W_edge, b_edge);
        mmagemm_kernel<<<N_NODES / 128, 256, SM_TOT>>>(
            l, b_gcn + l * HDIM,
            bn_g + l * HDIM, bn_b + l * HDIM, bn_m + l * HDIM, bn_v + l * HDIM);
    }

    pool_kernel<<<N_NODES / 512, 256>>>(batch);
    final_kernel<<<N_GRAPHS, HDIM>>>(gx, W_gproj, b_gproj, W_gcomb, b_gcomb, out);
}

// round 17
// speedup vs baseline: 1.2783x; 1.1081x over previous
#include <cuda_runtime.h>
#include <cuda_fp16.h>
#include <cuda_bf16.h>
#include <cstdint>

#define N_NODES 131072
#define N_EDGES 2097152
#define E_PAD   (N_EDGES + 16 * N_NODES)   // padded CSR slots (pad-to-16)
#define N_GRAPHS 64
#define DIN 64
#define HDIM 128
#define EPSV 1e-5f

// ---------------- scratch (device globals: allocation-free) ----------------
__device__ __align__(128) __half d_h16[((size_t)N_NODES + 1) * HDIM];  // 32 MB + sentinel row
__device__ __align__(128) __half d_t16[(size_t)N_NODES * HDIM];        // 32 MB fp16 (streamed)
__device__ __align__(128) uint2  d_edge[E_PAD];                        // {col, half2 attr} 32 MB
__device__ __align__(128) int    d_degi[N_NODES];
__device__ __align__(128) int    d_cnt[N_NODES];                       // seeded with starts
__device__ __align__(128) int    d_start[N_NODES + 1];
__device__ __align__(128) float  d_inv[N_NODES];
__device__ __align__(128) int    d_bsum[128];
// layer GEMM B-fragments (fp16): [layer][kstep 8][ntile 16][lane 32][reg 2]
__device__ __align__(128) uint32_t d_wfrag[3 * 8 * 16 * 32 * 2];
// input GEMM B-fragments (bf16 hi/lo): [hi/lo][kstep 4][ntile 16][lane 32][reg 2]
__device__ __align__(128) uint32_t d_wfragin[2 * 4 * 16 * 32 * 2];
__device__ __align__(128) float  d_gsum[N_GRAPHS * HDIM];
__device__ __align__(128) float  d_gcnt[N_GRAPHS];

// ---------------- helpers ----------------
__device__ __forceinline__ void red4(float* p, float4 v) {
    asm volatile("red.global.add.v4.f32 [%0], {%1,%2,%3,%4};"
                 :: "l"(p), "f"(v.x), "f"(v.y), "f"(v.z), "f"(v.w) : "memory");
}
__device__ __forceinline__ float4 h16_to_f4(uint2 u) {
    __half2* p = (__half2*)&u;
    float2 f0 = __half22float2(p[0]);
    float2 f1 = __half22float2(p[1]);
    return make_float4(f0.x, f0.y, f1.x, f1.y);
}
__device__ __forceinline__ void mma_bf16(float* d, uint32_t a0, uint32_t a1, uint32_t a2,
                                         uint32_t a3, uint32_t b0, uint32_t b1) {
    asm volatile(
        "mma.sync.aligned.m16n8k16.row.col.f32.bf16.bf16.f32 "
        "{%0,%1,%2,%3}, {%4,%5,%6,%7}, {%8,%9}, {%0,%1,%2,%3};"
        : "+f"(d[0]), "+f"(d[1]), "+f"(d[2]), "+f"(d[3])
        : "r"(a0), "r"(a1), "r"(a2), "r"(a3), "r"(b0), "r"(b1));
}
__device__ __forceinline__ void mma_f16(float* d, uint32_t a0, uint32_t a1, uint32_t a2,
                                        uint32_t a3, uint32_t b0, uint32_t b1) {
    asm volatile(
        "mma.sync.aligned.m16n8k16.row.col.f32.f16.f16.f32 "
        "{%0,%1,%2,%3}, {%4,%5,%6,%7}, {%8,%9}, {%0,%1,%2,%3};"
        : "+f"(d[0]), "+f"(d[1]), "+f"(d[2]), "+f"(d[3])
        : "r"(a0), "r"(a1), "r"(a2), "r"(a3), "r"(b0), "r"(b1));
}

// ---------------- K1: degree count + fused init (weight frags, zeroing) ----------------
__global__ __launch_bounds__(256) void deg_init_kernel(const int* __restrict__ row,
                                                       const float* __restrict__ Wg,
                                                       const float* __restrict__ Win) {
    int i = blockIdx.x * blockDim.x + threadIdx.x;   // 2M threads
    atomicAdd(&d_degi[row[i]], 1);

    if (i < 3 * 8 * 16 * 32 * 2) {       // 24576: layer GEMM B-frags (fp16)
        int r = i & 1;
        int lane = (i >> 1) & 31;
        int nt = (i >> 6) & 15;
        int ks = (i >> 10) & 7;
        int l = i >> 13;
        int tg = lane & 3;
        int g = lane >> 2;
        int k0 = ks * 16 + tg * 2 + r * 8;
        int n = nt * 8 + g;
        float w0 = __ldg(Wg + (size_t)l * HDIM * HDIM + k0 * HDIM + n);
        float w1 = __ldg(Wg + (size_t)l * HDIM * HDIM + (k0 + 1) * HDIM + n);
        __half2 h2 = __floats2half2_rn(w0, w1);
        d_wfrag[i] = *(uint32_t*)&h2;
    }
    if (i < 2 * 4 * 16 * 32 * 2) {       // 8192: input GEMM B-frags (bf16 hi/lo)
        int r = i & 1;
        int lane = (i >> 1) & 31;
        int nt = (i >> 6) & 15;
        int ks = (i >> 10) & 3;
        int s = (i >> 12) & 1;
        int tg = lane & 3;
        int g = lane >> 2;
        int k0 = ks * 16 + tg * 2 + r * 8;
        int n = nt * 8 + g;
        float w0 = __ldg(Win + k0 * HDIM + n);
        float w1 = __ldg(Win + (k0 + 1) * HDIM + n);
        __nv_bfloat16 v0, v1;
        if (s == 0) {
            v0 = __float2bfloat16(w0);
            v1 = __float2bfloat16(w1);
        } else {
            v0 = __float2bfloat16(w0 - __bfloat162float(__float2bfloat16(w0)));
            v1 = __float2bfloat16(w1 - __bfloat162float(__float2bfloat16(w1)));
        }
        d_wfragin[i] = (uint32_t)*(uint16_t*)&v0 | ((uint32_t)*(uint16_t*)&v1 << 16);
    }
    if (i < N_GRAPHS * HDIM) d_gsum[i] = 0.0f;
    if (i < N_GRAPHS) d_gcnt[i] = 0.0f;
    if (i < 16) ((uint4*)(d_h16 + (size_t)N_NODES * HDIM))[i] = make_uint4(0, 0, 0, 0);
}

// ---------------- K2a: per-block padded-deg sums ----------------
__global__ __launch_bounds__(256) void scanA_kernel() {
    __shared__ int sp[256];
    int tid = threadIdx.x;
    int4 dv = ((const int4*)d_degi)[blockIdx.x * 256 + tid];
    int s = ((dv.x + 15) & ~15) + ((dv.y + 15) & ~15) + ((dv.z + 15) & ~15) + ((dv.w + 15) & ~15);
    sp[tid] = s;
    __syncthreads();
    for (int off = 128; off > 0; off >>= 1) {
        if (tid < off) sp[tid] += sp[tid + off];
        __syncthreads();
    }
    if (tid == 0) d_bsum[blockIdx.x] = sp[0];
}

// ---------------- K2b: scan (block-base computed inline from d_bsum) ----------------
__global__ __launch_bounds__(256) void scanC_kernel() {
    __shared__ int sp[256];
    __shared__ int sb[128];
    int tid = threadIdx.x;
    int idx = blockIdx.x * 256 + tid;

    if (tid < 128) sb[tid] = d_bsum[tid];
    __syncthreads();
    for (int off = 1; off < 128; off <<= 1) {
        int v = (tid >= off && tid < 128) ? sb[tid - off] : 0;
        __syncthreads();
        if (tid < 128) sb[tid] += v;
        __syncthreads();
    }

    int4 dv = ((const int4*)d_degi)[idx];
    int p0 = (dv.x + 15) & ~15, p1 = (dv.y + 15) & ~15;
    int p2 = (dv.z + 15) & ~15, p3 = (dv.w + 15) & ~15;
    int s = p0 + p1 + p2 + p3;
    sp[tid] = s;
    __syncthreads();
    for (int off = 1; off < 256; off <<= 1) {
        int v = (tid >= off) ? sp[tid - off] : 0;
        __syncthreads();
        sp[tid] += v;
        __syncthreads();
    }
    int bbase = sb[blockIdx.x] - d_bsum[blockIdx.x];
    int base = bbase + sp[tid] - s;
    int4 st;
    st.x = base;
    st.y = base + p0;
    st.z = st.y + p1;
    st.w = st.z + p2;
    ((int4*)d_start)[idx] = st;
    ((int4*)d_cnt)[idx] = st;
    float4 iv;
    iv.x = 1.0f / (float)max(dv.x, 1);
    iv.y = 1.0f / (float)max(dv.y, 1);
    iv.z = 1.0f / (float)max(dv.z, 1);
    iv.w = 1.0f / (float)max(dv.w, 1);
    ((float4*)d_inv)[idx] = iv;
    if (blockIdx.x == 127 && tid == 127) d_start[N_NODES] = sb[127];
}

// ---------------- K3: counting-sort + pad-tail fill (fused; disjoint slots) ----------------
__global__ __launch_bounds__(256) void build_kernel(const int* __restrict__ row,
                                                    const int* __restrict__ col,
                                                    const float* __restrict__ eattr) {
    int e = blockIdx.x * blockDim.x + threadIdx.x;   // < E_PAD
    if (e < N_EDGES) {
        int r = __ldg(row + e);
        int pos = atomicAdd(&d_cnt[r], 1);           // pre-seeded with start[r]
        float2 a = __ldg((const float2*)eattr + e);
        __half2 ah = __floats2half2_rn(a.x, a.y);
        d_edge[pos] = make_uint2((uint32_t)__ldg(col + e), *(uint32_t*)&ah);
    } else {
        int ep = e - N_EDGES;                        // < 16*N_NODES
        int n = ep >> 4, k = ep & 15;
        int js = __ldg(d_start + n) + __ldg(d_degi + n);
        if (js + k < __ldg(d_start + n + 1))
            d_edge[js + k] = make_uint2((uint32_t)N_NODES, 0u);
    }
}

// ---------------- K5: CSR gather, factored weights + fp16 accumulation ----------------
__global__ __launch_bounds__(256) void gather_kernel(const float* __restrict__ We,
                                                     const float* __restrict__ be) {
    int lane = threadIdx.x & 31;
    int n = blockIdx.x * 8 + (threadIdx.x >> 5);

    int js = __ldg(d_start + n);
    int je = __ldg(d_start + n + 1);
    uint32_t lo8 = lane * 8;
    const char* hbase = (const char*)d_h16;

    __half2 z2 = __floats2half2_rn(0.f, 0.f);
    __half2 s0a = z2, s0b = z2, s1a = z2, s1b = z2, s2a = z2, s2b = z2;

    for (int j = js; j < je; j += 16) {
        uint4 er[8];
#pragma unroll
        for (int i = 0; i < 8; i++) er[i] = __ldg((const uint4*)(d_edge + j) + i);
        uint2 hv[16];
#pragma unroll
        for (int i = 0; i < 8; i++) {
            hv[2 * i]     = __ldg((const uint2*)(hbase + ((er[i].x << 8) + lo8)));
            hv[2 * i + 1] = __ldg((const uint2*)(hbase + ((er[i].z << 8) + lo8)));
        }
#pragma unroll
        for (int i = 0; i < 16; i++) {
            uint32_t au = (i & 1) ? er[i >> 1].w : er[i >> 1].y;
            __half2 ah = *(__half2*)&au;
            __half2 axx = __low2half2(ah);
            __half2 ayy = __high2half2(ah);
            __half2 v0 = ((__half2*)&hv[i])[0];
            __half2 v1 = ((__half2*)&hv[i])[1];
            s0a = __hfma2(v0, axx, s0a);
            s0b = __hfma2(v1, axx, s0b);
            s1a = __hfma2(v0, ayy, s1a);
            s1b = __hfma2(v1, ayy, s1b);
            s2a = __hadd2(s2a, v0);
            s2b = __hadd2(s2b, v1);
        }
    }

    // per-node combine (fp32)
    float4 w0 = __ldg((const float4*)We + lane);
    float4 w1 = __ldg((const float4*)(We + HDIM) + lane);
    float4 bb = __ldg((const float4*)be + lane);
    float2 f0a = __half22float2(s0a), f0b = __half22float2(s0b);
    float2 f1a = __half22float2(s1a), f1b = __half22float2(s1b);
    float2 f2a = __half22float2(s2a), f2b = __half22float2(s2b);

    float4 acc;
    acc.x = fmaf(w0.x, f0a.x, fmaf(w1.x, f1a.x, bb.x * f2a.x));
    acc.y = fmaf(w0.y, f0a.y, fmaf(w1.y, f1a.y, bb.y * f2a.y));
    acc.z = fmaf(w0.z, f0b.x, fmaf(w1.z, f1b.x, bb.z * f2b.x));
    acc.w = fmaf(w0.w, f0b.y, fmaf(w1.w, f1b.y, bb.w * f2b.y));

    float inv = __ldg(d_inv + n);
    float4 hv = h16_to_f4(__ldg((const uint2*)(hbase + (((uint32_t)n << 8) + lo8))));
    float tx = fmaf(acc.x, inv, hv.x);
    float ty = fmaf(acc.y, inv, hv.y);
    float tz = fmaf(acc.z, inv, hv.z);
    float tw = fmaf(acc.w, inv, hv.w);
    __half2 p0 = __floats2half2_rn(tx, ty);
    __half2 p1 = __floats2half2_rn(tz, tw);
    __stcs((uint2*)(d_t16 + (size_t)n * HDIM) + lane,
           make_uint2(*(uint32_t*)&p0, *(uint32_t*)&p1));   // evict-first
}

// ---------------- K6: input GEMM via mma (bf16 hi/lo): h16 = fp16(bf16(x) @ W + b) ----------------
#define SMI_A_BYTES (128 * 72 * 2)            // [128][72] bf16 = 18432
#define SMI_B_BYTES 32768                     // [2][4][16][32][2] u32
#define SMI_TOT (SMI_A_BYTES + SMI_B_BYTES)
__global__ __launch_bounds__(256, 2) void ingemm_kernel(const float* __restrict__ Ax,
                                                        const float* __restrict__ bias) {
    extern __shared__ char smem[];
    __nv_bfloat16* sA = (__nv_bfloat16*)smem;        // stride 72
    uint32_t* sB = (uint32_t*)(smem + SMI_A_BYTES);

    const int tid = threadIdx.x;
    const int lane = tid & 31;
    const int wid = tid >> 5;
    const int nb = blockIdx.x * 128;

    const float4* X = (const float4*)(Ax + (size_t)nb * DIN);
#pragma unroll
    for (int i = 0; i < 8; i++) {
        int q = tid + 256 * i;
        int m = q >> 4, c0 = (q & 15) * 4;
        float4 v = __ldcs(X + q);
        __nv_bfloat162 p0 = __floats2bfloat162_rn(v.x, v.y);
        __nv_bfloat162 p1 = __floats2bfloat162_rn(v.z, v.w);
        *(uint2*)(sA + m * 72 + c0) = make_uint2(*(uint32_t*)&p0, *(uint32_t*)&p1);
    }
    const uint4* BF = (const uint4*)d_wfragin;
#pragma unroll
    for (int i = 0; i < 8; i++) {
        int q = tid + 256 * i;
        ((uint4*)sB)[q] = __ldg(BF + q);
    }
    __syncthreads();

    const int g = lane >> 2, tg = lane & 3;
    float acc[16][4];
#pragma unroll
    for (int nt = 0; nt < 16; nt++)
#pragma unroll
        for (int c = 0; c < 4; c++) acc[nt][c] = 0.f;

    const __nv_bfloat16* ar0 = sA + (wid * 16 + g) * 72;
    const __nv_bfloat16* ar1 = ar0 + 8 * 72;

#pragma unroll
    for (int ks = 0; ks < 4; ks++) {
        int k0 = ks * 16 + tg * 2;
        uint32_t a0 = *(const uint32_t*)(ar0 + k0);
        uint32_t a1 = *(const uint32_t*)(ar1 + k0);
        uint32_t a2 = *(const uint32_t*)(ar0 + k0 + 8);
        uint32_t a3 = *(const uint32_t*)(ar1 + k0 + 8);
        const uint32_t* bh = sB + (ks * 16) * 64 + lane * 2;
        const uint32_t* bl = bh + 4 * 16 * 64;
#pragma unroll
        for (int nt = 0; nt < 16; nt++) {
            uint2 bhv = *(const uint2*)(bh + nt * 64);
            uint2 blv = *(const uint2*)(bl + nt * 64);
            mma_bf16(acc[nt], a0, a1, a2, a3, bhv.x, bhv.y);
            mma_bf16(acc[nt], a0, a1, a2, a3, blv.x, blv.y);
        }
    }

    int r0 = nb + wid * 16 + g;
    __half* om0 = d_h16 + (size_t)r0 * HDIM;
    __half* om1 = om0 + 8 * HDIM;
#pragma unroll
    for (int nt = 0; nt < 16; nt++) {
        int c = nt * 8 + tg * 2;
        float b0 = __ldg(bias + c), b1 = __ldg(bias + c + 1);
        *(__half2*)(om0 + c) = __floats2half2_rn(acc[nt][0] + b0, acc[nt][1] + b1);
        *(__half2*)(om1 + c) = __floats2half2_rn(acc[nt][2] + b0, acc[nt][3] + b1);
    }
}

// ---------------- K7: mma.sync fp16 layer GEMM: h16 = fp16(relu(BN(t16 @ W + b))) ----------------
#define SM_A_BYTES 34816                      // [128][136] fp16
#define SM_B_BYTES 32768                      // [8][16][32][2] u32
#define SM_TOT (SM_A_BYTES + SM_B_BYTES + 1024)
__global__ __launch_bounds__(256, 2) void mmagemm_kernel(int layer,
                                                         const float* __restrict__ bias,
                                                         const float* __restrict__ gamma,
                                                         const float* __restrict__ beta,
                                                         const float* __restrict__ mean,
                                                         const float* __restrict__ var) {
    extern __shared__ char smem[];
    __half* sA = (__half*)smem;                               // stride 136
    uint32_t* sB = (uint32_t*)(smem + SM_A_BYTES);
    float* sBN = (float*)(smem + SM_A_BYTES + SM_B_BYTES);

    const int tid = threadIdx.x;
    const int lane = tid & 31;
    const int wid = tid >> 5;
    const int nb = blockIdx.x * 128;

    if (tid < 128) {
        float g = __ldg(gamma + tid);
        float v = __ldg(var + tid);
        float m = __ldg(mean + tid);
        float bt = __ldg(beta + tid);
        float b = __ldg(bias + tid);
        float sc = g * rsqrtf(v + EPSV);
        sBN[tid] = sc;
        sBN[128 + tid] = fmaf(b - m, sc, bt);
    }

    // stage A: raw fp16 copy [128][128] -> [128][136] (streaming read)
    const uint4* T = (const uint4*)(d_t16 + (size_t)nb * HDIM);
#pragma unroll
    for (int i = 0; i < 8; i++) {
        int q = tid + 256 * i;
        int m = q >> 4, c0 = (q & 15) * 8;
        *(uint4*)(sA + m * 136 + c0) = __ldcs(T + q);
    }
    // stage B frags (fp16, 32 KB)
    const uint4* BF = (const uint4*)(d_wfrag + layer * 8192);
#pragma unroll
    for (int i = 0; i < 8; i++) {
        int q = tid + 256 * i;
        ((uint4*)sB)[q] = __ldg(BF + q);
    }
    __syncthreads();

    const int g = lane >> 2, tg = lane & 3;
    float acc[16][4];
#pragma unroll
    for (int nt = 0; nt < 16; nt++)
#pragma unroll
        for (int c = 0; c < 4; c++) acc[nt][c] = 0.f;

    const __half* ar0 = sA + (wid * 16 + g) * 136;
    const __half* ar1 = ar0 + 8 * 136;

#pragma unroll
    for (int ks = 0; ks < 8; ks++) {
        int k0 = ks * 16 + tg * 2;
        uint32_t a0 = *(const uint32_t*)(ar0 + k0);
        uint32_t a1 = *(const uint32_t*)(ar1 + k0);
        uint32_t a2 = *(const uint32_t*)(ar0 + k0 + 8);
        uint32_t a3 = *(const uint32_t*)(ar1 + k0 + 8);
        const uint32_t* bh = sB + (ks * 16) * 64 + lane * 2;
#pragma unroll
        for (int nt = 0; nt < 16; nt++) {
            uint2 bhv = *(const uint2*)(bh + nt * 64);
            mma_f16(acc[nt], a0, a1, a2, a3, bhv.x, bhv.y);
        }
    }

    int r0 = nb + wid * 16 + g;
    __half* om0 = d_h16 + (size_t)r0 * HDIM;
    __half* om1 = om0 + 8 * HDIM;
#pragma unroll
    for (int nt = 0; nt < 16; nt++) {
        int c = nt * 8 + tg * 2;
        float sc0 = sBN[c], sc1 = sBN[c + 1];
        float sh0 = sBN[128 + c], sh1 = sBN[128 + c + 1];
        float o00 = fmaxf(fmaf(acc[nt][0], sc0, sh0), 0.f);
        float o01 = fmaxf(fmaf(acc[nt][1], sc1, sh1), 0.f);
        float o10 = fmaxf(fmaf(acc[nt][2], sc0, sh0), 0.f);
        float o11 = fmaxf(fmaf(acc[nt][3], sc1, sh1), 0.f);
        *(__half2*)(om0 + c) = __floats2half2_rn(o00, o01);
        *(__half2*)(om1 + c) = __floats2half2_rn(o10, o11);
    }
}

// ---------------- K8: global mean-pool (batch sorted, reads h16) ----------------
__global__ __launch_bounds__(256) void pool_kernel(const int* __restrict__ batch) {
    int tx = threadIdx.x & 31;
    int ty = threadIdx.x >> 5;
    int base = blockIdx.x * 512;

    float4 acc = make_float4(0.f, 0.f, 0.f, 0.f);
    float cnt = 0.f;
    int curg = -1;

    for (int j = 0; j < 64; j++) {
        int n = base + ty + j * 8;
        int g = __ldg(batch + n);
        if (g != curg) {
            if (curg >= 0) {
                red4(d_gsum + curg * HDIM + 4 * tx, acc);
                if (tx == 0) atomicAdd(&d_gcnt[curg], cnt);
            }
            curg = g;
            acc = make_float4(0.f, 0.f, 0.f, 0.f);
            cnt = 0.f;
        }
        float4 h4 = h16_to_f4(((const uint2*)(d_h16 + (size_t)n * HDIM))[tx]);
        acc.x += h4.x; acc.y += h4.y; acc.z += h4.z; acc.w += h4.w;
        cnt += 1.f;
    }
    if (curg >= 0) {
        red4(d_gsum + curg * HDIM + 4 * tx, acc);
        if (tx == 0) atomicAdd(&d_gcnt[curg], cnt);
    }
}

// ---------------- K9: head ----------------
__global__ __launch_bounds__(128) void final_kernel(const float* __restrict__ gx,
                                                    const float* __restrict__ Wgp,
                                                    const float* __restrict__ bgp,
                                                    const float* __restrict__ Wgc,
                                                    const float* __restrict__ bgc,
                                                    float* __restrict__ out) {
    int g = blockIdx.x;
    int t = threadIdx.x;
    __shared__ float sg[HDIM];
    __shared__ float sgp[32];

    float c = fmaxf(__ldg(&d_gcnt[g]), 1.0f);
    sg[t] = d_gsum[g * HDIM + t] / c;
    if (t < 32) {
        float acc = __ldg(bgp + t);
        for (int d = 0; d < 6; d++)
            acc = fmaf(__ldg(gx + g * 6 + d), __ldg(Wgp + d * 32 + t), acc);
        sgp[t] = fmaxf(acc, 0.f);
    }
    __syncthreads();

    float acc = __ldg(bgc + t);
#pragma unroll 4
    for (int k = 0; k < HDIM; k++)
        acc = fmaf(sg[k], __ldg(Wgc + (size_t)k * HDIM + t), acc);
#pragma unroll 4
    for (int k = 0; k < 32; k++)
        acc = fmaf(sgp[k], __ldg(Wgc + (size_t)(HDIM + k) * HDIM + t), acc);
    out[g * HDIM + t] = acc;
}

// ---------------- launch ----------------
extern "C" void kernel_launch(void* const* d_in, const int* in_sizes, int n_in,
                              void* d_out, int out_size) {
    const float* x       = (const float*)d_in[0];
    const float* eattr   = (const float*)d_in[1];
    const float* gx      = (const float*)d_in[2];
    const float* W_in    = (const float*)d_in[3];
    const float* b_in    = (const float*)d_in[4];
    const float* W_edge  = (const float*)d_in[5];
    const float* b_edge  = (const float*)d_in[6];
    const float* W_gcn   = (const float*)d_in[7];
    const float* b_gcn   = (const float*)d_in[8];
    const float* bn_g    = (const float*)d_in[9];
    const float* bn_b    = (const float*)d_in[10];
    const float* bn_m    = (const float*)d_in[11];
    const float* bn_v    = (const float*)d_in[12];
    const float* W_gproj = (const float*)d_in[13];
    const float* b_gproj = (const float*)d_in[14];
    const float* W_gcomb = (const float*)d_in[15];
    const float* b_gcomb = (const float*)d_in[16];
    const int*   row     = (const int*)d_in[17];
    const int*   col     = (const int*)d_in[18];
    const int*   batch   = (const int*)d_in[19];
    float* out = (float*)d_out;

    cudaFuncSetAttribute(ingemm_kernel, cudaFuncAttributeMaxDynamicSharedMemorySize,
                         SMI_TOT);
    cudaFuncSetAttribute(mmagemm_kernel, cudaFuncAttributeMaxDynamicSharedMemorySize,
                         SM_TOT);

    void* degi_ptr = nullptr;
    cudaGetSymbolAddress(&degi_ptr, d_degi);
    cudaMemsetAsync(degi_ptr, 0, N_NODES * sizeof(int));

    deg_init_kernel<<<N_EDGES / 256, 256>>>(row, W_gcn, W_in);
    scanA_kernel<<<128, 256>>>();
    scanC_kernel<<<128, 256>>>();
    build_kernel<<<E_PAD / 256, 256>>>(row, col, eattr);

    ingemm_kernel<<<N_NODES / 128, 256, SMI_TOT>>>(x, b_in);

    for (int l = 0; l < 3; l++) {
        gather_kernel<<<N_NODES / 8, 256>>>(W_edge, b_edge);
        mmagemm_kernel<<<N_NODES / 128, 256, SM_TOT>>>(
            l, b_gcn + l * HDIM,
            bn_g + l * HDIM, bn_b + l * HDIM, bn_m + l * HDIM, bn_v + l * HDIM);
    }

    pool_kernel<<<N_NODES / 512, 256>>>(batch);
    final_kernel<<<N_GRAPHS, HDIM>>>(gx, W_gproj, b_gproj, W_gcomb, b_gcomb, out);
}